// round 5
// baseline (speedup 1.0000x reference)
#include <cuda_runtime.h>

#define D 512
#define D4 (D / 4)
#define EPS 1e-9f
#define NBLOCKS 444   // 3 CTAs/SM x 148 SMs, one balanced wave at occ=3

// Accumulators: [0]=sum_e, [1]=sum_e2, [2]=sum_t, [3]=sum_t2, [4]=sum_et
// Zero-initialized at module load; the last block re-zeroes after consuming,
// so "g_acc == 0, g_ticket == 0 at kernel entry" holds on every graph replay.
__device__ float g_acc[5 * D];
__device__ unsigned int g_ticket;

__global__ void __launch_bounds__(512, 3) stats_finalize_kernel(
        const float4* __restrict__ e,
        const float4* __restrict__ t,
        int B_rows,
        float* __restrict__ out,
        float B) {
    const int tid = threadIdx.x;
    const int c4  = tid & 127;          // float4 column group (4 columns)
    const int sub = tid >> 7;           // row substream 0..3

    // Balanced contiguous row range for this block.
    const long long r0 = ((long long)blockIdx.x * B_rows) / NBLOCKS;
    const long long r1 = ((long long)(blockIdx.x + 1) * B_rows) / NBLOCKS;

    float4 se  = {0.f, 0.f, 0.f, 0.f};
    float4 se2 = {0.f, 0.f, 0.f, 0.f};
    float4 st  = {0.f, 0.f, 0.f, 0.f};
    float4 st2 = {0.f, 0.f, 0.f, 0.f};
    float4 set = {0.f, 0.f, 0.f, 0.f};

    const float4* ep = e + (r0 + sub) * D4 + c4;
    const float4* tp = t + (r0 + sub) * D4 + c4;
    const long long n = r1 - (r0 + sub);   // rows in this substream, stride 4

    #pragma unroll 2
    for (long long i = 0; i * 4 < n; ++i) {
        float4 ev = ep[i * 4 * D4];
        float4 tv = tp[i * 4 * D4];
        se.x += ev.x;  se.y += ev.y;  se.z += ev.z;  se.w += ev.w;
        se2.x += ev.x * ev.x;  se2.y += ev.y * ev.y;
        se2.z += ev.z * ev.z;  se2.w += ev.w * ev.w;
        st.x += tv.x;  st.y += tv.y;  st.z += tv.z;  st.w += tv.w;
        st2.x += tv.x * tv.x;  st2.y += tv.y * tv.y;
        st2.z += tv.z * tv.z;  st2.w += tv.w * tv.w;
        set.x += ev.x * tv.x;  set.y += ev.y * tv.y;
        set.z += ev.z * tv.z;  set.w += ev.w * tv.w;
    }

    // ---- merge 4 substreams through shared memory ----
    __shared__ float4 sdata[4][5][128];   // [sub][stat][c4] = 40 KB
    sdata[sub][0][c4] = se;
    sdata[sub][1][c4] = se2;
    sdata[sub][2][c4] = st;
    sdata[sub][3][c4] = st2;
    sdata[sub][4][c4] = set;
    __syncthreads();

    if (tid < 128) {
        #pragma unroll
        for (int s = 0; s < 5; ++s) {
            float4 a = sdata[0][s][c4];
            float4 b = sdata[1][s][c4];
            float4 c = sdata[2][s][c4];
            float4 d = sdata[3][s][c4];
            float vx = a.x + b.x + c.x + d.x;
            float vy = a.y + b.y + c.y + d.y;
            float vz = a.z + b.z + c.z + d.z;
            float vw = a.w + b.w + c.w + d.w;
            atomicAdd(&g_acc[s * D + c4 * 4 + 0], vx);
            atomicAdd(&g_acc[s * D + c4 * 4 + 1], vy);
            atomicAdd(&g_acc[s * D + c4 * 4 + 2], vz);
            atomicAdd(&g_acc[s * D + c4 * 4 + 3], vw);
        }
    }

    // ---- last-block-done finalize ----
    __threadfence();
    __syncthreads();

    __shared__ bool is_last;
    if (tid == 0) {
        unsigned int t_ = atomicAdd(&g_ticket, 1u);
        is_last = (t_ == (unsigned int)(gridDim.x - 1));
    }
    __syncthreads();
    if (!is_last) return;

    const int col = tid;   // 512 threads = 512 columns
    float fse  = __ldcg(&g_acc[0 * D + col]);
    float fse2 = __ldcg(&g_acc[1 * D + col]);
    float fst  = __ldcg(&g_acc[2 * D + col]);
    float fst2 = __ldcg(&g_acc[3 * D + col]);
    float fset = __ldcg(&g_acc[4 * D + col]);

    // Re-zero for the next graph replay.
    g_acc[0 * D + col] = 0.f;
    g_acc[1 * D + col] = 0.f;
    g_acc[2 * D + col] = 0.f;
    g_acc[3 * D + col] = 0.f;
    g_acc[4 * D + col] = 0.f;
    if (col == 0) g_ticket = 0u;

    float me = fse / B;
    float mt = fst / B;
    float var_e = (fse2 - B * me * me) / (B - 1.0f);
    float var_t = (fst2 - B * mt * mt) / (B - 1.0f);
    float sd_e = sqrtf(fmaxf(var_e, 0.0f)) + EPS;
    float sd_t = sqrtf(fmaxf(var_t, 0.0f)) + EPS;

    float cov = fset - B * me * mt;
    float c = cov / (sd_e * sd_t) / B;
    float d = 1.0f - c;
    float partial = d * d;

    __shared__ float red[D];
    red[col] = partial;
    __syncthreads();
    #pragma unroll
    for (int s = 256; s > 0; s >>= 1) {
        if (col < s) red[col] += red[col + s];
        __syncthreads();
    }
    if (col == 0) out[0] = red[0];
}

extern "C" void kernel_launch(void* const* d_in, const int* in_sizes, int n_in,
                              void* d_out, int out_size) {
    const float* e = (const float*)d_in[0];
    const float* t = (const float*)d_in[1];
    float* out = (float*)d_out;

    const long long total = in_sizes[0];
    const int B = (int)(total / D);          // 65536

    stats_finalize_kernel<<<NBLOCKS, 512>>>((const float4*)e, (const float4*)t,
                                            B, out, (float)B);
}

// round 6
// speedup vs baseline: 1.3050x; 1.3050x over previous
#include <cuda_runtime.h>

#define D 512
#define EPS 1e-9f
#define NCTAS 148                 // 1 CTA per SM (forced by 192KB smem)
#define SROWS 8                   // rows per pipeline stage
#define NSTAGES 6
#define STAGE_FLOATS (SROWS * D)  // 4096 floats = 16KB per array per stage
#define SMEM_BYTES (NSTAGES * 2 * STAGE_FLOATS * 4)   // 192 KB

// Accumulators: [0]=sum_e, [1]=sum_e2, [2]=sum_t, [3]=sum_t2, [4]=sum_et
// Zero at module load; last block re-zeroes after consuming, so the invariant
// "g_acc == 0, g_ticket == 0 at kernel entry" holds on every graph replay.
__device__ float g_acc[5 * D];
__device__ unsigned int g_ticket;

__device__ __forceinline__ void cp16(float* sdst, const float* gsrc) {
    unsigned saddr = (unsigned)__cvta_generic_to_shared(sdst);
    asm volatile("cp.async.cg.shared.global [%0], [%1], 16;" :: "r"(saddr), "l"(gsrc));
}

__device__ __forceinline__ void issue_stage(
        float* smem, const float* __restrict__ e, const float* __restrict__ t,
        long long r0, int nrows, int s, int tid) {
    if (s * SROWS < nrows) {
        float* se_ = smem + (s % NSTAGES) * 2 * STAGE_FLOATS;
        float* st_ = se_ + STAGE_FLOATS;
        const long long gbase = (r0 + (long long)s * SROWS) * D;
        #pragma unroll
        for (int k = 0; k < 2; ++k) {
            const int fo = (tid + k * 512) * 4;        // 16B chunk offset
            if (s * SROWS + fo / D < nrows) {          // row guard (chunks never straddle rows)
                cp16(se_ + fo, e + gbase + fo);
                cp16(st_ + fo, t + gbase + fo);
            }
        }
    }
    asm volatile("cp.async.commit_group;");            // one group per stage, always
}

extern __shared__ float smem[];

__global__ void __launch_bounds__(512, 1) stats_finalize_kernel(
        const float* __restrict__ e,
        const float* __restrict__ t,
        int B_rows,
        float* __restrict__ out,
        float B) {
    const int tid = threadIdx.x;          // thread = column (0..511)

    // Balanced contiguous row range for this block (442 or 443 rows).
    const long long r0 = ((long long)blockIdx.x * B_rows) / NCTAS;
    const long long r1 = ((long long)(blockIdx.x + 1) * B_rows) / NCTAS;
    const int nrows = (int)(r1 - r0);
    const int nst = (nrows + SROWS - 1) / SROWS;

    // Prologue: fill NSTAGES-1 stages -> 160KB in flight.
    #pragma unroll
    for (int s = 0; s < NSTAGES - 1; ++s)
        issue_stage(smem, e, t, r0, nrows, s, tid);

    float a0 = 0.f, a1 = 0.f, a2 = 0.f, a3 = 0.f, a4 = 0.f;

    for (int i = 0; i < nst; ++i) {
        asm volatile("cp.async.wait_group %0;" :: "n"(NSTAGES - 2));
        __syncthreads();                  // stage i visible to all threads

        const float* se_ = smem + (i % NSTAGES) * 2 * STAGE_FLOATS;
        const float* st_ = se_ + STAGE_FLOATS;
        const int rmax = nrows - i * SROWS;

        if (rmax >= SROWS) {
            #pragma unroll
            for (int r = 0; r < SROWS; ++r) {
                float ev = se_[r * D + tid];
                float tv = st_[r * D + tid];
                a0 += ev;  a1 += ev * ev;
                a2 += tv;  a3 += tv * tv;
                a4 += ev * tv;
            }
        } else {
            for (int r = 0; r < rmax; ++r) {
                float ev = se_[r * D + tid];
                float tv = st_[r * D + tid];
                a0 += ev;  a1 += ev * ev;
                a2 += tv;  a3 += tv * tv;
                a4 += ev * tv;
            }
        }

        __syncthreads();                  // all threads done with buffer (i-1)%NSTAGES
        issue_stage(smem, e, t, r0, nrows, i + NSTAGES - 1, tid);
    }

    asm volatile("cp.async.wait_group 0;");   // drain (remaining groups are empty)

    atomicAdd(&g_acc[0 * D + tid], a0);
    atomicAdd(&g_acc[1 * D + tid], a1);
    atomicAdd(&g_acc[2 * D + tid], a2);
    atomicAdd(&g_acc[3 * D + tid], a3);
    atomicAdd(&g_acc[4 * D + tid], a4);

    // ---- last-block-done finalize ----
    __threadfence();                 // order this block's atomics before ticket
    __syncthreads();

    __shared__ bool is_last;
    if (tid == 0) {
        unsigned int t_ = atomicAdd(&g_ticket, 1u);
        is_last = (t_ == (unsigned int)(gridDim.x - 1));
    }
    __syncthreads();
    if (!is_last) return;

    // Last block: all atomics visible at L2; read with .cg (atomics bypass L1).
    float fse  = __ldcg(&g_acc[0 * D + tid]);
    float fse2 = __ldcg(&g_acc[1 * D + tid]);
    float fst  = __ldcg(&g_acc[2 * D + tid]);
    float fst2 = __ldcg(&g_acc[3 * D + tid]);
    float fset = __ldcg(&g_acc[4 * D + tid]);

    // Re-zero for the next graph replay.
    g_acc[0 * D + tid] = 0.f;
    g_acc[1 * D + tid] = 0.f;
    g_acc[2 * D + tid] = 0.f;
    g_acc[3 * D + tid] = 0.f;
    g_acc[4 * D + tid] = 0.f;
    if (tid == 0) g_ticket = 0u;

    float me = fse / B;
    float mt = fst / B;
    float var_e = (fse2 - B * me * me) / (B - 1.0f);   // ddof=1
    float var_t = (fst2 - B * mt * mt) / (B - 1.0f);
    float sd_e = sqrtf(fmaxf(var_e, 0.0f)) + EPS;
    float sd_t = sqrtf(fmaxf(var_t, 0.0f)) + EPS;

    float cov = fset - B * me * mt;
    float c = cov / (sd_e * sd_t) / B;
    float d = 1.0f - c;
    float partial = d * d;

    float* red = smem;               // reuse pipeline smem for the reduction
    __syncthreads();
    red[tid] = partial;
    __syncthreads();
    #pragma unroll
    for (int s = 256; s > 0; s >>= 1) {
        if (tid < s) red[tid] += red[tid + s];
        __syncthreads();
    }
    if (tid == 0) out[0] = red[0];
}

extern "C" void kernel_launch(void* const* d_in, const int* in_sizes, int n_in,
                              void* d_out, int out_size) {
    const float* e = (const float*)d_in[0];
    const float* t = (const float*)d_in[1];
    float* out = (float*)d_out;

    const long long total = in_sizes[0];
    const int B = (int)(total / D);          // 65536

    cudaFuncSetAttribute(stats_finalize_kernel,
                         cudaFuncAttributeMaxDynamicSharedMemorySize, SMEM_BYTES);
    stats_finalize_kernel<<<NCTAS, 512, SMEM_BYTES>>>(e, t, B, out, (float)B);
}

// round 7
// speedup vs baseline: 1.3692x; 1.0492x over previous
#include <cuda_runtime.h>

#define D 512
#define EPS 1e-9f
#define NBLOCKS 512

// Accumulators: [0]=sum_e, [1]=sum_e2, [2]=sum_t, [3]=sum_t2, [4]=sum_et
// Zero at module load; last block re-zeroes after consuming, so the invariant
// "g_acc == 0, g_ticket == 0 at kernel entry" holds on every graph replay.
__device__ float g_acc[5 * D];
__device__ unsigned int g_ticket;

__global__ void __launch_bounds__(D) stats_finalize_kernel(
        const float* __restrict__ e,
        const float* __restrict__ t,
        int rows_per_block,
        float* __restrict__ out,
        float B) {
    const int col = threadIdx.x;                 // 512 threads = 512 columns
    const long long r0 = (long long)blockIdx.x * rows_per_block;

    float se = 0.f, se2 = 0.f, st = 0.f, st2 = 0.f, set = 0.f;

    const float* ep = e + r0 * D + col;
    const float* tp = t + r0 * D + col;

    #pragma unroll 4
    for (int r = 0; r < rows_per_block; ++r) {
        // Streaming loads (evict-first): this data is touched exactly once,
        // keep it from occupying L2 fill bandwidth.
        float ev = __ldcs(ep + (long long)r * D);
        float tv = __ldcs(tp + (long long)r * D);
        se  += ev;
        se2 += ev * ev;
        st  += tv;
        st2 += tv * tv;
        set += ev * tv;
    }

    atomicAdd(&g_acc[0 * D + col], se);
    atomicAdd(&g_acc[1 * D + col], se2);
    atomicAdd(&g_acc[2 * D + col], st);
    atomicAdd(&g_acc[3 * D + col], st2);
    atomicAdd(&g_acc[4 * D + col], set);

    // ---- last-block-done finalize ----
    __threadfence();                 // order this block's atomics before ticket
    __syncthreads();                 // all threads' atomics issued + fenced

    __shared__ bool is_last;
    if (col == 0) {
        unsigned int t_ = atomicAdd(&g_ticket, 1u);
        is_last = (t_ == (unsigned int)(gridDim.x - 1));
    }
    __syncthreads();
    if (!is_last) return;

    // Last block: all atomics visible at L2; read with .cg (atomics bypass L1).
    float fse  = __ldcg(&g_acc[0 * D + col]);
    float fse2 = __ldcg(&g_acc[1 * D + col]);
    float fst  = __ldcg(&g_acc[2 * D + col]);
    float fst2 = __ldcg(&g_acc[3 * D + col]);
    float fset = __ldcg(&g_acc[4 * D + col]);

    // Re-zero for the next graph replay.
    g_acc[0 * D + col] = 0.f;
    g_acc[1 * D + col] = 0.f;
    g_acc[2 * D + col] = 0.f;
    g_acc[3 * D + col] = 0.f;
    g_acc[4 * D + col] = 0.f;
    if (col == 0) g_ticket = 0u;

    float me = fse / B;
    float mt = fst / B;
    float var_e = (fse2 - B * me * me) / (B - 1.0f);   // ddof=1
    float var_t = (fst2 - B * mt * mt) / (B - 1.0f);
    float sd_e = sqrtf(fmaxf(var_e, 0.0f)) + EPS;
    float sd_t = sqrtf(fmaxf(var_t, 0.0f)) + EPS;

    float cov = fset - B * me * mt;
    float c = cov / (sd_e * sd_t) / B;
    float d = 1.0f - c;
    float partial = d * d;

    // Block reduction: warp shuffles, then one warp over 16 partials.
    __shared__ float red[16];
    #pragma unroll
    for (int o = 16; o > 0; o >>= 1)
        partial += __shfl_down_sync(0xffffffffu, partial, o);
    if ((col & 31) == 0) red[col >> 5] = partial;
    __syncthreads();
    if (col < 32) {
        float v = (col < 16) ? red[col] : 0.f;
        #pragma unroll
        for (int o = 8; o > 0; o >>= 1)
            v += __shfl_down_sync(0xffffffffu, v, o);
        if (col == 0) out[0] = v;
    }
}

extern "C" void kernel_launch(void* const* d_in, const int* in_sizes, int n_in,
                              void* d_out, int out_size) {
    const float* e = (const float*)d_in[0];
    const float* t = (const float*)d_in[1];
    float* out = (float*)d_out;

    const long long total = in_sizes[0];
    const int B = (int)(total / D);          // 65536
    const int rows_per_block = B / NBLOCKS;  // 128

    stats_finalize_kernel<<<NBLOCKS, D>>>(e, t, rows_per_block, out, (float)B);
}

// round 8
// speedup vs baseline: 1.5432x; 1.1270x over previous
#include <cuda_runtime.h>
#include <cstdint>

#define D 512
#define EPS 1e-9f
#define NCTAS 148                  // persistent: 1 CTA/SM (forced by smem)
#define SROWS 8                    // rows per stage
#define NSTAGES 6
#define ROW_BYTES (D * 4)          // 2048
#define STAGE_FLOATS (SROWS * D)   // 4096 floats = 16KB per array per stage
#define SMEM_BYTES (NSTAGES * 2 * STAGE_FLOATS * 4)   // 192 KB

// Accumulators: [0]=sum_e, [1]=sum_e2, [2]=sum_t, [3]=sum_t2, [4]=sum_et
// Zero at module load; last block re-zeroes after consuming, so the invariant
// "g_acc == 0, g_ticket == 0 at kernel entry" holds on every graph replay.
__device__ float g_acc[5 * D];
__device__ unsigned int g_ticket;

__device__ __forceinline__ unsigned s2u(const void* p) {
    return (unsigned)__cvta_generic_to_shared(p);
}

__device__ __forceinline__ void bulk_ld(unsigned sdst, const float* gsrc,
                                        unsigned bytes, unsigned mb) {
    asm volatile(
        "cp.async.bulk.shared::cluster.global.mbarrier::complete_tx::bytes "
        "[%0], [%1], %2, [%3];"
        :: "r"(sdst), "l"(gsrc), "r"(bytes), "r"(mb) : "memory");
}

__device__ __forceinline__ void mbar_wait(unsigned mb, unsigned phase) {
    asm volatile(
        "{\n\t.reg .pred P;\n"
        "W%=:\n\t"
        "mbarrier.try_wait.parity.acquire.cta.shared::cta.b64 P, [%0], %1, 0x989680;\n\t"
        "@P bra.uni DONE%=;\n\t"
        "bra.uni W%=;\n"
        "DONE%=:\n\t}"
        :: "r"(mb), "r"(phase) : "memory");
}

extern __shared__ float smem[];

__global__ void __launch_bounds__(512, 1) stats_finalize_kernel(
        const float* __restrict__ e,
        const float* __restrict__ t,
        int B_rows,
        float* __restrict__ out,
        float B) {
    const int tid = threadIdx.x;          // thread = column (0..511)
    __shared__ uint64_t mbar[NSTAGES];

    // Balanced contiguous row range for this block (442 or 443 rows).
    const long long r0 = ((long long)blockIdx.x * B_rows) / NCTAS;
    const long long r1 = ((long long)(blockIdx.x + 1) * B_rows) / NCTAS;
    const int nrows = (int)(r1 - r0);
    const int nst = (nrows + SROWS - 1) / SROWS;

    if (tid == 0) {
        #pragma unroll
        for (int s = 0; s < NSTAGES; ++s)
            asm volatile("mbarrier.init.shared.b64 [%0], 1;"
                         :: "r"(s2u(&mbar[s])) : "memory");
        asm volatile("fence.proxy.async.shared::cta;" ::: "memory");
    }
    __syncthreads();

    // Producer helper (tid 0 only): issue stage s as two bulk copies.
    auto issue = [&](int s) {
        if (s >= nst) return;
        const int rows = min(SROWS, nrows - s * SROWS);
        const unsigned bytes = (unsigned)rows * ROW_BYTES;
        const int slot = s % NSTAGES;
        float* se_ = smem + slot * 2 * STAGE_FLOATS;
        float* st_ = se_ + STAGE_FLOATS;
        const unsigned mb = s2u(&mbar[slot]);
        asm volatile("mbarrier.arrive.expect_tx.shared.b64 _, [%0], %1;"
                     :: "r"(mb), "r"(2u * bytes) : "memory");
        const long long gr = (r0 + (long long)s * SROWS) * D;
        bulk_ld(s2u(se_), e + gr, bytes, mb);
        bulk_ld(s2u(st_), t + gr, bytes, mb);
    };

    // Prologue: 5 stages in flight (160 KB).
    if (tid == 0) {
        #pragma unroll
        for (int s = 0; s < NSTAGES - 1; ++s) issue(s);
    }

    float a0 = 0.f, a1 = 0.f, a2 = 0.f, a3 = 0.f, a4 = 0.f;

    for (int i = 0; i < nst; ++i) {
        const int slot = i % NSTAGES;
        const unsigned phase = (unsigned)((i / NSTAGES) & 1);
        mbar_wait(s2u(&mbar[slot]), phase);       // all 512 threads

        const float* se_ = smem + slot * 2 * STAGE_FLOATS;
        const float* st_ = se_ + STAGE_FLOATS;
        const int rmax = nrows - i * SROWS;

        if (rmax >= SROWS) {
            #pragma unroll
            for (int r = 0; r < SROWS; ++r) {
                float ev = se_[r * D + tid];
                float tv = st_[r * D + tid];
                a0 += ev;  a1 += ev * ev;
                a2 += tv;  a3 += tv * tv;
                a4 += ev * tv;
            }
        } else {
            for (int r = 0; r < rmax; ++r) {
                float ev = se_[r * D + tid];
                float tv = st_[r * D + tid];
                a0 += ev;  a1 += ev * ev;
                a2 += tv;  a3 += tv * tv;
                a4 += ev * tv;
            }
        }

        __syncthreads();              // everyone done with slot (i-1)%NSTAGES
        if (tid == 0) issue(i + NSTAGES - 1);
    }

    atomicAdd(&g_acc[0 * D + tid], a0);
    atomicAdd(&g_acc[1 * D + tid], a1);
    atomicAdd(&g_acc[2 * D + tid], a2);
    atomicAdd(&g_acc[3 * D + tid], a3);
    atomicAdd(&g_acc[4 * D + tid], a4);

    // ---- last-block-done finalize ----
    __threadfence();
    __syncthreads();

    __shared__ bool is_last;
    if (tid == 0) {
        unsigned int t_ = atomicAdd(&g_ticket, 1u);
        is_last = (t_ == (unsigned int)(gridDim.x - 1));
    }
    __syncthreads();
    if (!is_last) return;

    float fse  = __ldcg(&g_acc[0 * D + tid]);
    float fse2 = __ldcg(&g_acc[1 * D + tid]);
    float fst  = __ldcg(&g_acc[2 * D + tid]);
    float fst2 = __ldcg(&g_acc[3 * D + tid]);
    float fset = __ldcg(&g_acc[4 * D + tid]);

    // Re-zero for the next graph replay.
    g_acc[0 * D + tid] = 0.f;
    g_acc[1 * D + tid] = 0.f;
    g_acc[2 * D + tid] = 0.f;
    g_acc[3 * D + tid] = 0.f;
    g_acc[4 * D + tid] = 0.f;
    if (tid == 0) g_ticket = 0u;

    float me = fse / B;
    float mt = fst / B;
    float var_e = (fse2 - B * me * me) / (B - 1.0f);   // ddof=1
    float var_t = (fst2 - B * mt * mt) / (B - 1.0f);
    float sd_e = sqrtf(fmaxf(var_e, 0.0f)) + EPS;
    float sd_t = sqrtf(fmaxf(var_t, 0.0f)) + EPS;

    float cov = fset - B * me * mt;
    float c = cov / (sd_e * sd_t) / B;
    float d = 1.0f - c;
    float partial = d * d;

    // Block reduction: warp shuffles, then one warp over 16 partials.
    __shared__ float red[16];
    #pragma unroll
    for (int o = 16; o > 0; o >>= 1)
        partial += __shfl_down_sync(0xffffffffu, partial, o);
    if ((tid & 31) == 0) red[tid >> 5] = partial;
    __syncthreads();
    if (tid < 32) {
        float v = (tid < 16) ? red[tid] : 0.f;
        #pragma unroll
        for (int o = 8; o > 0; o >>= 1)
            v += __shfl_down_sync(0xffffffffu, v, o);
        if (tid == 0) out[0] = v;
    }
}

extern "C" void kernel_launch(void* const* d_in, const int* in_sizes, int n_in,
                              void* d_out, int out_size) {
    const float* e = (const float*)d_in[0];
    const float* t = (const float*)d_in[1];
    float* out = (float*)d_out;

    const long long total = in_sizes[0];
    const int B = (int)(total / D);          // 65536

    cudaFuncSetAttribute(stats_finalize_kernel,
                         cudaFuncAttributeMaxDynamicSharedMemorySize, SMEM_BYTES);
    stats_finalize_kernel<<<NCTAS, 512, SMEM_BYTES>>>(e, t, B, out, (float)B);
}